// round 2
// baseline (speedup 1.0000x reference)
#include <cuda_runtime.h>
#include <math_constants.h>

#define BATCH 32
#define SEQ   2048
#define CDIM  384
#define HDIM  64
#define M_TOT (BATCH*SEQ)

// scratch: q (pre-scaled), k, v  — [B*T, H] row-major
__device__ __align__(16) float g_k[M_TOT*HDIM];
__device__ __align__(16) float g_q[M_TOT*HDIM];
__device__ __align__(16) float g_v[M_TOT*HDIM];

// ---------------------------------------------------------------------------
// Projection: k/q/v = x @ W{k,q,v}.  M=65536, K=384, N=64.
// Block = 64 rows x 64 cols, 128 threads, 8x4 micro-tile per weight (x3).
// x stored TRANSPOSED in smem so A-fragment = 2x LDS.128.
// Inner iter: 5 LDS.128 per 96 FFMA.
// ---------------------------------------------------------------------------
__global__ __launch_bounds__(128) void proj_kernel(
    const float* __restrict__ x, const float* __restrict__ Wk,
    const float* __restrict__ Wq, const float* __restrict__ Wv)
{
    __shared__ __align__(16) float xst[32 * 68];     // [cc][r], stride 68
    __shared__ __align__(16) float ws[3][32][68];    // [w][cc][col]

    const int tid = threadIdx.x;
    const int tx = tid & 15;        // col group (4 cols)
    const int ty = tid >> 4;        // row group (8 rows), 0..7
    const int row0 = blockIdx.x * 64;

    float acc[3][8][4];
#pragma unroll
    for (int w = 0; w < 3; w++)
#pragma unroll
        for (int i = 0; i < 8; i++)
#pragma unroll
            for (int j = 0; j < 4; j++) acc[w][i][j] = 0.f;

    for (int c0 = 0; c0 < CDIM; c0 += 32) {
        // x tile 64 rows x 32 cc, loaded as f4 rows, stored transposed
#pragma unroll
        for (int t = 0; t < 4; t++) {
            int fidx = tid + t * 128;        // 0..511
            int r = fidx >> 3;               // 0..63
            int c4 = (fidx & 7) * 4;         // 0..28
            float4 xv = *(const float4*)&x[(size_t)(row0 + r) * CDIM + c0 + c4];
            xst[(c4 + 0) * 68 + r] = xv.x;
            xst[(c4 + 1) * 68 + r] = xv.y;
            xst[(c4 + 2) * 68 + r] = xv.z;
            xst[(c4 + 3) * 68 + r] = xv.w;
        }
        // weight tiles 32 x 64 each, natural layout, f4 stores
#pragma unroll
        for (int t = 0; t < 4; t++) {
            int fidx = tid + t * 128;        // 0..511
            int cc = fidx >> 4;              // 0..31
            int col = (fidx & 15) * 4;       // 0..60
            *(float4*)&ws[0][cc][col] = *(const float4*)&Wk[(c0 + cc) * HDIM + col];
            *(float4*)&ws[1][cc][col] = *(const float4*)&Wq[(c0 + cc) * HDIM + col];
            *(float4*)&ws[2][cc][col] = *(const float4*)&Wv[(c0 + cc) * HDIM + col];
        }
        __syncthreads();

#pragma unroll 8
        for (int cc = 0; cc < 32; cc++) {
            float4 a0 = *(const float4*)&xst[cc * 68 + ty * 8];
            float4 a1 = *(const float4*)&xst[cc * 68 + ty * 8 + 4];
            const float af[8] = {a0.x, a0.y, a0.z, a0.w, a1.x, a1.y, a1.z, a1.w};
#pragma unroll
            for (int w = 0; w < 3; w++) {
                float4 b4 = *(const float4*)&ws[w][cc][tx * 4];
                const float bf[4] = {b4.x, b4.y, b4.z, b4.w};
#pragma unroll
                for (int i = 0; i < 8; i++)
#pragma unroll
                    for (int j = 0; j < 4; j++)
                        acc[w][i][j] += af[i] * bf[j];
            }
        }
        __syncthreads();
    }

#pragma unroll
    for (int i = 0; i < 8; i++) {
        size_t off = (size_t)(row0 + ty * 8 + i) * HDIM + tx * 4;
        *(float4*)&g_k[off] = make_float4(acc[0][i][0], acc[0][i][1],
                                          acc[0][i][2], acc[0][i][3]);
        *(float4*)&g_q[off] = make_float4(acc[1][i][0] * 0.125f, acc[1][i][1] * 0.125f,
                                          acc[1][i][2] * 0.125f, acc[1][i][3] * 0.125f);
        *(float4*)&g_v[off] = make_float4(acc[2][i][0], acc[2][i][1],
                                          acc[2][i][2], acc[2][i][3]);
    }
}

// ---------------------------------------------------------------------------
// Flash attention (causal). Q-tile=128, K-tile=64, 128 threads, 8x8 micro-tile.
// tx = tid&7 (8 col-groups of 8), ty = tid>>3 (16 row-groups of 8).
// Inner GEMM iter: 4 LDS.128 per 64 FFMA.
// smem 100KB: qst [h][r] stride 132, kst [h][s] stride 68,
//             vs [s][h] stride 68, pst [s][r] stride 132.
// ---------------------------------------------------------------------------
#define QT 128
#define KT 64
#define ATT_SMEM ((64*132 + 64*68 + 64*68 + 64*132) * (int)sizeof(float))

__global__ __launch_bounds__(128) void attn_kernel(float* __restrict__ out)
{
    extern __shared__ __align__(16) float sm[];
    float* qst = sm;                       // [h*132 + r]
    float* kst = qst + 64 * 132;           // [h*68 + s]
    float* vs  = kst + 64 * 68;            // [s*68 + h]
    float* pst = vs  + 64 * 68;            // [s*132 + r]

    const int tid = threadIdx.x;
    const int tx = tid & 7;
    const int ty = tid >> 3;               // 0..15
    const int qt = (gridDim.x - 1) - blockIdx.x;   // heavy tiles first
    const int b  = blockIdx.y;
    const int qrow0 = qt * QT;
    const size_t base = (size_t)b * SEQ * HDIM;

    // load q tile 128x64, transposed scatter into qst
#pragma unroll
    for (int t = 0; t < 16; t++) {
        int fidx = tid + t * 128;          // 0..2047
        int r = fidx >> 4;                 // 0..127
        int h4 = (fidx & 15) * 4;
        float4 qv = *(const float4*)&g_q[base + (size_t)(qrow0 + r) * HDIM + h4];
        qst[(h4 + 0) * 132 + r] = qv.x;
        qst[(h4 + 1) * 132 + r] = qv.y;
        qst[(h4 + 2) * 132 + r] = qv.z;
        qst[(h4 + 3) * 132 + r] = qv.w;
    }

    float m[8], l[8], o[8][8];
#pragma unroll
    for (int i = 0; i < 8; i++) {
        m[i] = -CUDART_INF_F;
        l[i] = 0.f;
#pragma unroll
        for (int j = 0; j < 8; j++) o[i][j] = 0.f;
    }

    const int n_kt = 2 * qt + 2;
    for (int kt = 0; kt < n_kt; kt++) {
        __syncthreads();   // prior GEMM2 fully drained before overwriting tiles

        // k transposed, v natural
#pragma unroll
        for (int t = 0; t < 8; t++) {
            int fidx = tid + t * 128;      // 0..1023
            int s = fidx >> 4;             // 0..63
            int h4 = (fidx & 15) * 4;
            float4 kv = *(const float4*)&g_k[base + (size_t)(kt * KT + s) * HDIM + h4];
            kst[(h4 + 0) * 68 + s] = kv.x;
            kst[(h4 + 1) * 68 + s] = kv.y;
            kst[(h4 + 2) * 68 + s] = kv.z;
            kst[(h4 + 3) * 68 + s] = kv.w;
            float4 vv = *(const float4*)&g_v[base + (size_t)(kt * KT + s) * HDIM + h4];
            *(float4*)&vs[s * 68 + h4] = vv;
        }
        __syncthreads();

        // GEMM1: S = q @ k^T  (q pre-scaled by 0.125)
        float sacc[8][8];
#pragma unroll
        for (int i = 0; i < 8; i++)
#pragma unroll
            for (int j = 0; j < 8; j++) sacc[i][j] = 0.f;

#pragma unroll 8
        for (int h = 0; h < 64; h++) {
            float4 a0 = *(const float4*)&qst[h * 132 + ty * 8];
            float4 a1 = *(const float4*)&qst[h * 132 + ty * 8 + 4];
            float4 b0 = *(const float4*)&kst[h * 68 + tx * 8];
            float4 b1 = *(const float4*)&kst[h * 68 + tx * 8 + 4];
            const float af[8] = {a0.x, a0.y, a0.z, a0.w, a1.x, a1.y, a1.z, a1.w};
            const float bf[8] = {b0.x, b0.y, b0.z, b0.w, b1.x, b1.y, b1.z, b1.w};
#pragma unroll
            for (int i = 0; i < 8; i++)
#pragma unroll
                for (int j = 0; j < 8; j++)
                    sacc[i][j] += af[i] * bf[j];
        }

        // causal mask (only the last two k-tiles intersect the diagonal)
        if (kt >= 2 * qt) {
#pragma unroll
            for (int i = 0; i < 8; i++)
#pragma unroll
                for (int j = 0; j < 8; j++)
                    if (kt * KT + tx * 8 + j > qrow0 + ty * 8 + i)
                        sacc[i][j] = -CUDART_INF_F;
        }

        // online softmax: reductions over the 8-lane tx group
#pragma unroll
        for (int i = 0; i < 8; i++) {
            float r = sacc[i][0];
#pragma unroll
            for (int j = 1; j < 8; j++) r = fmaxf(r, sacc[i][j]);
#pragma unroll
            for (int off = 4; off > 0; off >>= 1)
                r = fmaxf(r, __shfl_xor_sync(0xffffffffu, r, off, 8));
            float mn = fmaxf(m[i], r);
            float alpha = __expf(m[i] - mn);
            m[i] = mn;
            float rsum = 0.f;
#pragma unroll
            for (int j = 0; j < 8; j++) {
                sacc[i][j] = __expf(sacc[i][j] - mn);
                rsum += sacc[i][j];
            }
#pragma unroll
            for (int off = 4; off > 0; off >>= 1)
                rsum += __shfl_xor_sync(0xffffffffu, rsum, off, 8);
            l[i] = l[i] * alpha + rsum;
#pragma unroll
            for (int j = 0; j < 8; j++) o[i][j] *= alpha;
        }

        // write P transposed [s][r], float4 over r
#pragma unroll
        for (int j = 0; j < 8; j++) {
            int s = tx * 8 + j;
            *(float4*)&pst[s * 132 + ty * 8] =
                make_float4(sacc[0][j], sacc[1][j], sacc[2][j], sacc[3][j]);
            *(float4*)&pst[s * 132 + ty * 8 + 4] =
                make_float4(sacc[4][j], sacc[5][j], sacc[6][j], sacc[7][j]);
        }
        __syncthreads();

        // GEMM2: O += P @ V
#pragma unroll 8
        for (int s = 0; s < 64; s++) {
            float4 p0 = *(const float4*)&pst[s * 132 + ty * 8];
            float4 p1 = *(const float4*)&pst[s * 132 + ty * 8 + 4];
            float4 v0 = *(const float4*)&vs[s * 68 + tx * 8];
            float4 v1 = *(const float4*)&vs[s * 68 + tx * 8 + 4];
            const float pf[8] = {p0.x, p0.y, p0.z, p0.w, p1.x, p1.y, p1.z, p1.w};
            const float vf[8] = {v0.x, v0.y, v0.z, v0.w, v1.x, v1.y, v1.z, v1.w};
#pragma unroll
            for (int i = 0; i < 8; i++)
#pragma unroll
                for (int j = 0; j < 8; j++)
                    o[i][j] += pf[i] * vf[j];
        }
    }

    // epilogue: normalize and store
#pragma unroll
    for (int i = 0; i < 8; i++) {
        float inv = 1.f / l[i];
        size_t off = base + (size_t)(qrow0 + ty * 8 + i) * HDIM + tx * 8;
        *(float4*)&out[off] = make_float4(o[i][0] * inv, o[i][1] * inv,
                                          o[i][2] * inv, o[i][3] * inv);
        *(float4*)&out[off + 4] = make_float4(o[i][4] * inv, o[i][5] * inv,
                                              o[i][6] * inv, o[i][7] * inv);
    }
}

// ---------------------------------------------------------------------------
extern "C" void kernel_launch(void* const* d_in, const int* in_sizes, int n_in,
                              void* d_out, int out_size)
{
    const float* x  = (const float*)d_in[0];
    const float* Wk = (const float*)d_in[1];
    const float* Wq = (const float*)d_in[2];
    const float* Wv = (const float*)d_in[3];
    float* out = (float*)d_out;

    proj_kernel<<<M_TOT / 64, 128>>>(x, Wk, Wq, Wv);

    cudaFuncSetAttribute(attn_kernel, cudaFuncAttributeMaxDynamicSharedMemorySize,
                         ATT_SMEM);
    dim3 grid(SEQ / QT, BATCH);
    attn_kernel<<<grid, 128, ATT_SMEM>>>(out);
}

// round 3
// speedup vs baseline: 3.4162x; 3.4162x over previous
#include <cuda_runtime.h>
#include <math_constants.h>
#include <cstdint>

#define BATCH 32
#define SEQ   2048
#define CDIM  384
#define HDIM  64
#define M_TOT (BATCH*SEQ)

// scratch: q (pre-scaled, tf32-rounded), k, v — [B*T, H] row-major
__device__ __align__(16) float g_k[M_TOT*HDIM];
__device__ __align__(16) float g_q[M_TOT*HDIM];
__device__ __align__(16) float g_v[M_TOT*HDIM];

__device__ __forceinline__ float f2tf(float f) {
    uint32_t r;
    asm("cvt.rna.tf32.f32 %0, %1;" : "=r"(r) : "f"(f));
    return __uint_as_float(r);
}

// D += A@B, m16n8k8 tf32, A row-major, B col-major
__device__ __forceinline__ void mma8(float* d, const uint32_t* a, uint32_t b0, uint32_t b1) {
    asm volatile("mma.sync.aligned.m16n8k8.row.col.f32.tf32.tf32.f32 "
        "{%0,%1,%2,%3}, {%4,%5,%6,%7}, {%8,%9}, {%0,%1,%2,%3};"
        : "+f"(d[0]), "+f"(d[1]), "+f"(d[2]), "+f"(d[3])
        : "r"(a[0]), "r"(a[1]), "r"(a[2]), "r"(a[3]), "r"(b0), "r"(b1));
}

// ---------------------------------------------------------------------------
// Projection: k/q/v = x @ W{k,q,v}.  M=65536, K=384, N=64, tf32 mma.
// 128 threads / 4 warps. Block M-tile 64. Warp: all 4 m16-tiles, 2 n8-tiles
// per weight. Outputs rounded to tf32 (q pre-scaled by 0.125).
// ---------------------------------------------------------------------------
__global__ __launch_bounds__(128) void proj_kernel(
    const float* __restrict__ x, const float* __restrict__ Wk,
    const float* __restrict__ Wq, const float* __restrict__ Wv)
{
    __shared__ __align__(16) float xs[64 * 36];      // [r][c] stride 36
    __shared__ __align__(16) float ws[3][32 * 72];   // [kc][col] stride 72

    const int tid  = threadIdx.x;
    const int lane = tid & 31;
    const int w    = tid >> 5;
    const int row0 = blockIdx.x * 64;

    float acc[3][4][2][4];
#pragma unroll
    for (int a = 0; a < 3; a++)
#pragma unroll
        for (int b = 0; b < 4; b++)
#pragma unroll
            for (int c = 0; c < 2; c++)
#pragma unroll
                for (int d = 0; d < 4; d++) acc[a][b][c][d] = 0.f;

    for (int c0 = 0; c0 < CDIM; c0 += 32) {
        __syncthreads();
        // x tile 64x32 -> tf32 -> smem
#pragma unroll
        for (int t = 0; t < 4; t++) {
            int fidx = tid + t * 128;            // 0..511
            int r = fidx >> 3, c4 = (fidx & 7) * 4;
            float4 v = *(const float4*)&x[(size_t)(row0 + r) * CDIM + c0 + c4];
            v.x = f2tf(v.x); v.y = f2tf(v.y); v.z = f2tf(v.z); v.w = f2tf(v.w);
            *(float4*)&xs[r * 36 + c4] = v;
        }
        // W tiles 32x64 x3 -> tf32 -> smem
#pragma unroll
        for (int ww = 0; ww < 3; ww++) {
            const float* W = (ww == 0) ? Wk : (ww == 1) ? Wq : Wv;
#pragma unroll
            for (int t = 0; t < 4; t++) {
                int fidx = tid + t * 128;        // 0..511
                int kc = fidx >> 4, col4 = (fidx & 15) * 4;
                float4 v = *(const float4*)&W[(c0 + kc) * HDIM + col4];
                v.x = f2tf(v.x); v.y = f2tf(v.y); v.z = f2tf(v.z); v.w = f2tf(v.w);
                *(float4*)&ws[ww][kc * 72 + col4] = v;
            }
        }
        __syncthreads();

#pragma unroll
        for (int kt = 0; kt < 4; kt++) {
            uint32_t a[4][4];
#pragma unroll
            for (int mt = 0; mt < 4; mt++) {
                int r = mt * 16 + (lane >> 2);
                int c = kt * 8 + (lane & 3);
                a[mt][0] = __float_as_uint(xs[r * 36 + c]);
                a[mt][1] = __float_as_uint(xs[(r + 8) * 36 + c]);
                a[mt][2] = __float_as_uint(xs[r * 36 + c + 4]);
                a[mt][3] = __float_as_uint(xs[(r + 8) * 36 + c + 4]);
            }
            int kr = kt * 8 + (lane & 3);
#pragma unroll
            for (int ww = 0; ww < 3; ww++)
#pragma unroll
                for (int ntl = 0; ntl < 2; ntl++) {
                    int n0 = (w * 2 + ntl) * 8 + (lane >> 2);
                    uint32_t b0 = __float_as_uint(ws[ww][kr * 72 + n0]);
                    uint32_t b1 = __float_as_uint(ws[ww][(kr + 4) * 72 + n0]);
#pragma unroll
                    for (int mt = 0; mt < 4; mt++)
                        mma8(acc[ww][mt][ntl], a[mt], b0, b1);
                }
        }
    }

    // epilogue: round to tf32 and store (q scaled by 0.125)
#pragma unroll
    for (int mt = 0; mt < 4; mt++)
#pragma unroll
        for (int ntl = 0; ntl < 2; ntl++) {
            int rg = row0 + mt * 16 + (lane >> 2);
            int cg = (w * 2 + ntl) * 8 + 2 * (lane & 3);
            size_t o0 = (size_t)rg * HDIM + cg;
            size_t o1 = (size_t)(rg + 8) * HDIM + cg;
            const float* ak = acc[0][mt][ntl];
            const float* aq = acc[1][mt][ntl];
            const float* av = acc[2][mt][ntl];
            *(float2*)&g_k[o0] = make_float2(f2tf(ak[0]), f2tf(ak[1]));
            *(float2*)&g_k[o1] = make_float2(f2tf(ak[2]), f2tf(ak[3]));
            *(float2*)&g_q[o0] = make_float2(f2tf(aq[0] * 0.125f), f2tf(aq[1] * 0.125f));
            *(float2*)&g_q[o1] = make_float2(f2tf(aq[2] * 0.125f), f2tf(aq[3] * 0.125f));
            *(float2*)&g_v[o0] = make_float2(f2tf(av[0]), f2tf(av[1]));
            *(float2*)&g_v[o1] = make_float2(f2tf(av[2]), f2tf(av[3]));
        }
}

// ---------------------------------------------------------------------------
// Flash attention (causal), tf32 mma. Q-tile 64, K-tile 64, 4 warps.
// Warp w: rows 16w..16w+15, full n=64. Q-fragments preloaded to registers.
// P round-trips through warp-private smem (aliased onto warp's q rows).
// smem: qs/ps [64][68], ks [64][68], vs [64][72]  (53 KB dynamic).
// ---------------------------------------------------------------------------
#define ATT_SMEM ((64*68 + 64*68 + 64*72) * (int)sizeof(float))

__global__ __launch_bounds__(128) void attn_kernel(float* __restrict__ out)
{
    extern __shared__ __align__(16) float sm[];
    float* qs = sm;                  // stride 68; later reused as ps
    float* ks = sm + 64 * 68;        // stride 68
    float* vs = sm + 2 * 64 * 68;    // stride 72

    const int tid  = threadIdx.x;
    const int lane = tid & 31;
    const int w    = tid >> 5;
    const int qt   = (gridDim.x - 1) - blockIdx.x;   // heavy tiles first
    const int b    = blockIdx.y;
    const int qrow0 = qt * 64;
    const size_t base = (size_t)b * SEQ * HDIM;

    // load q tile 64x64 (already tf32-rounded)
#pragma unroll
    for (int t = 0; t < 8; t++) {
        int fidx = tid + t * 128;            // 0..1023
        int r = fidx >> 4, h4 = (fidx & 15) * 4;
        *(float4*)&qs[r * 68 + h4] =
            *(const float4*)&g_q[base + (size_t)(qrow0 + r) * HDIM + h4];
    }
    __syncthreads();

    // preload q fragments (A-operand) for all 8 k-steps
    uint32_t qa[8][4];
    {
        int r = w * 16 + (lane >> 2);
#pragma unroll
        for (int kt8 = 0; kt8 < 8; kt8++) {
            int c = kt8 * 8 + (lane & 3);
            qa[kt8][0] = __float_as_uint(qs[r * 68 + c]);
            qa[kt8][1] = __float_as_uint(qs[(r + 8) * 68 + c]);
            qa[kt8][2] = __float_as_uint(qs[r * 68 + c + 4]);
            qa[kt8][3] = __float_as_uint(qs[(r + 8) * 68 + c + 4]);
        }
    }
    // qs rows 16w..16w+15 now warp-private -> reuse as ps (no block sync needed)
    float* ps = qs + w * 16 * 68;

    float o[8][4];
#pragma unroll
    for (int nt = 0; nt < 8; nt++)
#pragma unroll
        for (int e = 0; e < 4; e++) o[nt][e] = 0.f;
    float m0 = -CUDART_INF_F, m1 = -CUDART_INF_F, l0 = 0.f, l1 = 0.f;

    for (int kt = 0; kt <= qt; kt++) {
        __syncthreads();   // all warps done reading ks/vs from previous iter
#pragma unroll
        for (int t = 0; t < 8; t++) {
            int fidx = tid + t * 128;
            int r = fidx >> 4, h4 = (fidx & 15) * 4;
            *(float4*)&ks[r * 68 + h4] =
                *(const float4*)&g_k[base + (size_t)(kt * 64 + r) * HDIM + h4];
            *(float4*)&vs[r * 72 + h4] =
                *(const float4*)&g_v[base + (size_t)(kt * 64 + r) * HDIM + h4];
        }
        __syncthreads();

        // GEMM1: S = q @ k^T
        float s[8][4];
#pragma unroll
        for (int nt = 0; nt < 8; nt++)
#pragma unroll
            for (int e = 0; e < 4; e++) s[nt][e] = 0.f;

#pragma unroll
        for (int kt8 = 0; kt8 < 8; kt8++) {
            int hc = kt8 * 8 + (lane & 3);
#pragma unroll
            for (int nt = 0; nt < 8; nt++) {
                int sr = nt * 8 + (lane >> 2);
                uint32_t b0 = __float_as_uint(ks[sr * 68 + hc]);
                uint32_t b1 = __float_as_uint(ks[sr * 68 + hc + 4]);
                mma8(s[nt], qa[kt8], b0, b1);
            }
        }

        // causal mask on diagonal tile (rows/cols share the same tile origin)
        if (kt == qt) {
            int rg = 16 * w + (lane >> 2);
            int c0 = 2 * (lane & 3);
#pragma unroll
            for (int nt = 0; nt < 8; nt++) {
                int cg = c0 + 8 * nt;
                if (cg     > rg)     s[nt][0] = -CUDART_INF_F;
                if (cg + 1 > rg)     s[nt][1] = -CUDART_INF_F;
                if (cg     > rg + 8) s[nt][2] = -CUDART_INF_F;
                if (cg + 1 > rg + 8) s[nt][3] = -CUDART_INF_F;
            }
        }

        // online softmax (two rows per thread; reduce over 4-lane quads)
        float mx0 = -CUDART_INF_F, mx1 = -CUDART_INF_F;
#pragma unroll
        for (int nt = 0; nt < 8; nt++) {
            mx0 = fmaxf(mx0, fmaxf(s[nt][0], s[nt][1]));
            mx1 = fmaxf(mx1, fmaxf(s[nt][2], s[nt][3]));
        }
        mx0 = fmaxf(mx0, __shfl_xor_sync(0xffffffffu, mx0, 1, 4));
        mx0 = fmaxf(mx0, __shfl_xor_sync(0xffffffffu, mx0, 2, 4));
        mx1 = fmaxf(mx1, __shfl_xor_sync(0xffffffffu, mx1, 1, 4));
        mx1 = fmaxf(mx1, __shfl_xor_sync(0xffffffffu, mx1, 2, 4));

        float nm0 = fmaxf(m0, mx0), nm1 = fmaxf(m1, mx1);
        float al0 = __expf(m0 - nm0), al1 = __expf(m1 - nm1);
        m0 = nm0; m1 = nm1;

        float sum0 = 0.f, sum1 = 0.f;
#pragma unroll
        for (int nt = 0; nt < 8; nt++) {
            s[nt][0] = __expf(s[nt][0] - nm0); sum0 += s[nt][0];
            s[nt][1] = __expf(s[nt][1] - nm0); sum0 += s[nt][1];
            s[nt][2] = __expf(s[nt][2] - nm1); sum1 += s[nt][2];
            s[nt][3] = __expf(s[nt][3] - nm1); sum1 += s[nt][3];
        }
        sum0 += __shfl_xor_sync(0xffffffffu, sum0, 1, 4);
        sum0 += __shfl_xor_sync(0xffffffffu, sum0, 2, 4);
        sum1 += __shfl_xor_sync(0xffffffffu, sum1, 1, 4);
        sum1 += __shfl_xor_sync(0xffffffffu, sum1, 2, 4);
        l0 = l0 * al0 + sum0;
        l1 = l1 * al1 + sum1;
#pragma unroll
        for (int nt = 0; nt < 8; nt++) {
            o[nt][0] *= al0; o[nt][1] *= al0;
            o[nt][2] *= al1; o[nt][3] *= al1;
        }

        // store P (tf32-rounded) to warp-private smem
        {
            int r = lane >> 2;
#pragma unroll
            for (int nt = 0; nt < 8; nt++) {
                int c = nt * 8 + 2 * (lane & 3);
                *(float2*)&ps[r * 68 + c] = make_float2(f2tf(s[nt][0]), f2tf(s[nt][1]));
                *(float2*)&ps[(r + 8) * 68 + c] = make_float2(f2tf(s[nt][2]), f2tf(s[nt][3]));
            }
        }
        __syncwarp();

        // GEMM2: O += P @ V
#pragma unroll
        for (int st = 0; st < 8; st++) {
            uint32_t pa[4];
            int r = lane >> 2, c = st * 8 + (lane & 3);
            pa[0] = __float_as_uint(ps[r * 68 + c]);
            pa[1] = __float_as_uint(ps[(r + 8) * 68 + c]);
            pa[2] = __float_as_uint(ps[r * 68 + c + 4]);
            pa[3] = __float_as_uint(ps[(r + 8) * 68 + c + 4]);
            int vr = st * 8 + (lane & 3);
#pragma unroll
            for (int nt = 0; nt < 8; nt++) {
                int hc = nt * 8 + (lane >> 2);
                uint32_t b0 = __float_as_uint(vs[vr * 72 + hc]);
                uint32_t b1 = __float_as_uint(vs[(vr + 4) * 72 + hc]);
                mma8(o[nt], pa, b0, b1);
            }
        }
    }

    // epilogue
    float i0 = 1.f / l0, i1 = 1.f / l1;
    int rg = qrow0 + 16 * w + (lane >> 2);
#pragma unroll
    for (int nt = 0; nt < 8; nt++) {
        int cg = nt * 8 + 2 * (lane & 3);
        *(float2*)&out[base + (size_t)rg * HDIM + cg] =
            make_float2(o[nt][0] * i0, o[nt][1] * i0);
        *(float2*)&out[base + (size_t)(rg + 8) * HDIM + cg] =
            make_float2(o[nt][2] * i1, o[nt][3] * i1);
    }
}

// ---------------------------------------------------------------------------
extern "C" void kernel_launch(void* const* d_in, const int* in_sizes, int n_in,
                              void* d_out, int out_size)
{
    const float* x  = (const float*)d_in[0];
    const float* Wk = (const float*)d_in[1];
    const float* Wq = (const float*)d_in[2];
    const float* Wv = (const float*)d_in[3];
    float* out = (float*)d_out;

    proj_kernel<<<M_TOT / 64, 128>>>(x, Wk, Wq, Wv);

    cudaFuncSetAttribute(attn_kernel, cudaFuncAttributeMaxDynamicSharedMemorySize,
                         ATT_SMEM);
    dim3 grid(SEQ / 64, BATCH);
    attn_kernel<<<grid, 128, ATT_SMEM>>>(out);
}